// round 1
// baseline (speedup 1.0000x reference)
#include <cuda_runtime.h>

#define NN 50000
#define DD 256
#define NLAYER 3
#define NEXP 4
#define NED 1600000

// ---------------- device scratch (static, no allocation) ----------------
__device__ float g_h[NN * DD];          // 51.2 MB
__device__ float g_agg[NN * DD];        // 51.2 MB
__device__ float g_Y[NEXP * NN * DD];   // 204.8 MB
__device__ float g_gates[NN * NEXP];
__device__ int   g_indptr[NN + 1];
__device__ int   g_cursor[NN];
__device__ int   g_col[NED];
__device__ int   g_indeg[NN];
__device__ int   g_outdeg[NN];
__device__ float g_norm_src[NN];
__device__ float g_norm_dst[NN];
__device__ float g_colsum[NEXP * DD];
__device__ float g_colsq[NEXP * DD];
__device__ float g_sA[NEXP * DD];       // BN fold: z*A + B
__device__ float g_sB[NEXP * DD];

// ---------------- graph preprocessing ----------------
__global__ void k_zero_deg() {
    int i = blockIdx.x * blockDim.x + threadIdx.x;
    if (i < NN) { g_indeg[i] = 0; g_outdeg[i] = 0; }
}

__global__ void k_degree(const int* __restrict__ ei) {
    int i = blockIdx.x * blockDim.x + threadIdx.x;
    if (i < NED) {
        atomicAdd(&g_outdeg[ei[i]], 1);
        atomicAdd(&g_indeg[ei[NED + i]], 1);
    }
}

// single-block exclusive scan of g_indeg -> g_indptr
__global__ void k_scan() {
    __shared__ int sbuf[1024];
    __shared__ int scarry;
    int tid = threadIdx.x;
    if (tid == 0) scarry = 0;
    __syncthreads();
    for (int base = 0; base < NN; base += 1024) {
        int i = base + tid;
        int v = (i < NN) ? g_indeg[i] : 0;
        sbuf[tid] = v;
        __syncthreads();
        for (int off = 1; off < 1024; off <<= 1) {
            int t = (tid >= off) ? sbuf[tid - off] : 0;
            __syncthreads();
            sbuf[tid] += t;
            __syncthreads();
        }
        if (i < NN) g_indptr[i] = scarry + sbuf[tid] - v;
        int tot = sbuf[1023];
        __syncthreads();
        if (tid == 0) scarry += tot;
        __syncthreads();
    }
    if (threadIdx.x == 0) g_indptr[NN] = scarry;
}

__global__ void k_norm() {
    int i = blockIdx.x * blockDim.x + threadIdx.x;
    if (i < NN) {
        float od = (float)g_outdeg[i];
        float id = (float)g_indeg[i];
        g_norm_src[i] = rsqrtf(fmaxf(od, 1.0f));
        g_norm_dst[i] = rsqrtf(fmaxf(id, 1.0f));
        g_cursor[i] = g_indptr[i];
    }
}

__global__ void k_fill(const int* __restrict__ ei) {
    int i = blockIdx.x * blockDim.x + threadIdx.x;
    if (i < NED) {
        int s = ei[i];
        int d = ei[NED + i];
        int p = atomicAdd(&g_cursor[d], 1);
        g_col[p] = s;
    }
}

// ---------------- embedding ----------------
__global__ void k_embed(const int* __restrict__ x, const float* __restrict__ emb) {
    int i = blockIdx.x * blockDim.x + threadIdx.x;  // over NN*64 float4
    if (i >= NN * 64) return;
    int n = i >> 6;
    int c = i & 63;
    ((float4*)g_h)[i] = ((const float4*)emb)[(long)x[n] * 64 + c];
}

// ---------------- gating: top-2 softmax ----------------
__global__ void k_gate(const float* __restrict__ wg) {  // wg = w_gate + l*DD*NEXP
    int gw = (blockIdx.x * blockDim.x + threadIdx.x) >> 5;
    int lane = threadIdx.x & 31;
    if (gw >= NN) return;
    const float* hrow = g_h + gw * DD;
    const float4* w4 = (const float4*)wg;  // [DD] float4 (E=4 contiguous)
    float ax = 0.f, ay = 0.f, az = 0.f, aw = 0.f;
#pragma unroll
    for (int j = 0; j < 8; j++) {
        int k = lane + 32 * j;
        float hv = hrow[k];
        float4 w = w4[k];
        ax += hv * w.x; ay += hv * w.y; az += hv * w.z; aw += hv * w.w;
    }
#pragma unroll
    for (int off = 16; off; off >>= 1) {
        ax += __shfl_xor_sync(0xFFFFFFFFu, ax, off);
        ay += __shfl_xor_sync(0xFFFFFFFFu, ay, off);
        az += __shfl_xor_sync(0xFFFFFFFFu, az, off);
        aw += __shfl_xor_sync(0xFFFFFFFFu, aw, off);
    }
    if (lane == 0) {
        float v[4] = {ax, ay, az, aw};
        int i1 = 0;
#pragma unroll
        for (int e = 1; e < 4; e++) if (v[e] > v[i1]) i1 = e;
        int i2 = (i1 == 0) ? 1 : 0;
#pragma unroll
        for (int e = 0; e < 4; e++) if (e != i1 && v[e] > v[i2]) i2 = e;
        float t = __expf(v[i2] - v[i1]);
        float inv = 1.0f / (1.0f + t);
        float go[4] = {0.f, 0.f, 0.f, 0.f};
        go[i1] = inv;
        go[i2] = t * inv;
        *(float4*)&g_gates[gw * 4] = make_float4(go[0], go[1], go[2], go[3]);
    }
}

// ---------------- SpMM: agg = Dd^-1/2 A Ds^-1/2 h ----------------
__global__ void k_spmm() {
    int gw = (blockIdx.x * blockDim.x + threadIdx.x) >> 5;
    int lane = threadIdx.x & 31;
    if (gw >= NN) return;
    int beg = g_indptr[gw];
    int end = g_indptr[gw + 1];
    float4 a0 = make_float4(0.f, 0.f, 0.f, 0.f);
    float4 a1 = make_float4(0.f, 0.f, 0.f, 0.f);
    const float4* h4 = (const float4*)g_h;
    for (int p = beg; p < end; p++) {
        int s = __ldg(&g_col[p]);
        float ns = __ldg(&g_norm_src[s]);
        float4 v0 = h4[s * 64 + lane];
        float4 v1 = h4[s * 64 + 32 + lane];
        a0.x += ns * v0.x; a0.y += ns * v0.y; a0.z += ns * v0.z; a0.w += ns * v0.w;
        a1.x += ns * v1.x; a1.y += ns * v1.y; a1.z += ns * v1.z; a1.w += ns * v1.w;
    }
    float nd = g_norm_dst[gw];
    float4* o = (float4*)g_agg;
    a0.x *= nd; a0.y *= nd; a0.z *= nd; a0.w *= nd;
    a1.x *= nd; a1.y *= nd; a1.z *= nd; a1.w *= nd;
    o[gw * 64 + lane] = a0;
    o[gw * 64 + 32 + lane] = a1;
}

// ---------------- stats zero ----------------
__global__ void k_zero_stats() {
    int i = blockIdx.x * blockDim.x + threadIdx.x;
    if (i < NEXP * DD) { g_colsum[i] = 0.f; g_colsq[i] = 0.f; }
}

// ---------------- expert GEMM: Y[e] = agg @ W[e] + b[e], fused col stats ----------------
__global__ __launch_bounds__(256, 2) void k_gemm(const float* __restrict__ Wall,
                                                 const float* __restrict__ ball) {
    __shared__ float As[8][128];
    __shared__ float Bs[8][128];
    __shared__ float red[16][128];
    int e = blockIdx.z;
    const float* W = Wall + e * DD * DD;
    int row0 = blockIdx.x * 128;
    int col0 = blockIdx.y * 128;
    int tid = threadIdx.x;
    int tx = tid & 15, ty = tid >> 4;
    float acc[8][8];
#pragma unroll
    for (int i = 0; i < 8; i++)
#pragma unroll
        for (int j = 0; j < 8; j++) acc[i][j] = 0.f;
    int arow = tid >> 1, ak = (tid & 1) * 4;
    int bk = tid >> 5, bf = (tid & 31) * 4;
    int gr_a = row0 + arow;
    for (int k0 = 0; k0 < DD; k0 += 8) {
        float4 av = make_float4(0.f, 0.f, 0.f, 0.f);
        if (gr_a < NN) av = *(const float4*)(g_agg + gr_a * DD + k0 + ak);
        As[ak + 0][arow] = av.x;
        As[ak + 1][arow] = av.y;
        As[ak + 2][arow] = av.z;
        As[ak + 3][arow] = av.w;
        *(float4*)&Bs[bk][bf] = *(const float4*)(W + (k0 + bk) * DD + col0 + bf);
        __syncthreads();
#pragma unroll
        for (int k = 0; k < 8; k++) {
            float ar[8], br[8];
#pragma unroll
            for (int i = 0; i < 8; i++) ar[i] = As[k][ty * 8 + i];
#pragma unroll
            for (int j = 0; j < 8; j++) br[j] = Bs[k][tx * 8 + j];
#pragma unroll
            for (int i = 0; i < 8; i++)
#pragma unroll
                for (int j = 0; j < 8; j++) acc[i][j] += ar[i] * br[j];
        }
        __syncthreads();
    }
    // epilogue: bias, store Y, column sum/sumsq partials
    const float* bv = ball + e * DD + col0;
    float bias[8];
#pragma unroll
    for (int j = 0; j < 8; j++) bias[j] = bv[tx * 8 + j];
    float psum[8], psq[8];
#pragma unroll
    for (int j = 0; j < 8; j++) { psum[j] = 0.f; psq[j] = 0.f; }
    float* Yout = g_Y + e * NN * DD;
#pragma unroll
    for (int i = 0; i < 8; i++) {
        int gr = row0 + ty * 8 + i;
        if (gr < NN) {
            float v[8];
#pragma unroll
            for (int j = 0; j < 8; j++) {
                v[j] = acc[i][j] + bias[j];
                psum[j] += v[j];
                psq[j] += v[j] * v[j];
            }
            float* o = Yout + gr * DD + col0 + tx * 8;
            *(float4*)o = make_float4(v[0], v[1], v[2], v[3]);
            *(float4*)(o + 4) = make_float4(v[4], v[5], v[6], v[7]);
        }
    }
    __syncthreads();
#pragma unroll
    for (int j = 0; j < 8; j++) red[ty][tx * 8 + j] = psum[j];
    __syncthreads();
    if (tid < 128) {
        float s = 0.f;
#pragma unroll
        for (int r = 0; r < 16; r++) s += red[r][tid];
        atomicAdd(&g_colsum[e * DD + col0 + tid], s);
    }
    __syncthreads();
#pragma unroll
    for (int j = 0; j < 8; j++) red[ty][tx * 8 + j] = psq[j];
    __syncthreads();
    if (tid < 128) {
        float s = 0.f;
#pragma unroll
        for (int r = 0; r < 16; r++) s += red[r][tid];
        atomicAdd(&g_colsq[e * DD + col0 + tid], s);
    }
}

// ---------------- BN fold ----------------
__global__ void k_stats(const float* __restrict__ gamma, const float* __restrict__ beta) {
    int i = blockIdx.x * blockDim.x + threadIdx.x;
    if (i < NEXP * DD) {
        float mu = g_colsum[i] * (1.0f / NN);
        float ex2 = g_colsq[i] * (1.0f / NN);
        float var = fmaxf(ex2 - mu * mu, 0.f);
        float a = rsqrtf(var + 1e-5f) * gamma[i];
        g_sA[i] = a;
        g_sB[i] = beta[i] - mu * a;
    }
}

// ---------------- gated combine + residual-relu ----------------
__global__ void k_combine(float* __restrict__ dout, int last) {
    int gw = (blockIdx.x * blockDim.x + threadIdx.x) >> 5;
    int lane = threadIdx.x & 31;
    if (gw >= NN) return;
    float4 g4 = *(const float4*)&g_gates[gw * 4];
    float ga[4] = {g4.x, g4.y, g4.z, g4.w};
    const float4* Y4 = (const float4*)g_Y;
    const float4* A4 = (const float4*)g_sA;
    const float4* B4 = (const float4*)g_sB;
    float4 m0 = make_float4(0.f, 0.f, 0.f, 0.f);
    float4 m1 = make_float4(0.f, 0.f, 0.f, 0.f);
#pragma unroll
    for (int e = 0; e < 4; e++) {
        float ge = ga[e];
        if (ge == 0.f) continue;
        int base = (e * NN + gw) * 64;
        float4 y0 = Y4[base + lane];
        float4 y1 = Y4[base + 32 + lane];
        float4 a0 = A4[e * 64 + lane];
        float4 a1 = A4[e * 64 + 32 + lane];
        float4 b0 = B4[e * 64 + lane];
        float4 b1 = B4[e * 64 + 32 + lane];
        m0.x += ge * (y0.x * a0.x + b0.x);
        m0.y += ge * (y0.y * a0.y + b0.y);
        m0.z += ge * (y0.z * a0.z + b0.z);
        m0.w += ge * (y0.w * a0.w + b0.w);
        m1.x += ge * (y1.x * a1.x + b1.x);
        m1.y += ge * (y1.y * a1.y + b1.y);
        m1.z += ge * (y1.z * a1.z + b1.z);
        m1.w += ge * (y1.w * a1.w + b1.w);
    }
    // h = h_moe + relu(h_moe)
    m0.x += fmaxf(m0.x, 0.f); m0.y += fmaxf(m0.y, 0.f);
    m0.z += fmaxf(m0.z, 0.f); m0.w += fmaxf(m0.w, 0.f);
    m1.x += fmaxf(m1.x, 0.f); m1.y += fmaxf(m1.y, 0.f);
    m1.z += fmaxf(m1.z, 0.f); m1.w += fmaxf(m1.w, 0.f);
    float4* hh = (float4*)g_h;
    hh[gw * 64 + lane] = m0;
    hh[gw * 64 + 32 + lane] = m1;
    if (last) {
        float4* oo = (float4*)dout;
        oo[gw * 64 + lane] = m0;
        oo[gw * 64 + 32 + lane] = m1;
    }
}

// ---------------- launch ----------------
extern "C" void kernel_launch(void* const* d_in, const int* in_sizes, int n_in,
                              void* d_out, int out_size) {
    const int*   x        = (const int*)d_in[0];
    const int*   ei       = (const int*)d_in[1];
    const float* emb      = (const float*)d_in[2];
    const float* w_gate   = (const float*)d_in[3];
    const float* conv_W   = (const float*)d_in[4];
    const float* conv_b   = (const float*)d_in[5];
    const float* bn_gamma = (const float*)d_in[6];
    const float* bn_beta  = (const float*)d_in[7];
    float* out = (float*)d_out;

    // graph preprocessing (CSR by dst)
    k_zero_deg<<<(NN + 255) / 256, 256>>>();
    k_degree<<<(NED + 255) / 256, 256>>>(ei);
    k_scan<<<1, 1024>>>();
    k_norm<<<(NN + 255) / 256, 256>>>();
    k_fill<<<(NED + 255) / 256, 256>>>(ei);
    k_embed<<<(NN * 64 + 255) / 256, 256>>>(x, emb);

    const int warpsBlocks = (NN * 32 + 255) / 256;  // warp per node, 8 warps/block
    for (int l = 0; l < NLAYER; l++) {
        k_gate<<<warpsBlocks, 256>>>(w_gate + l * DD * NEXP);
        k_spmm<<<warpsBlocks, 256>>>();
        k_zero_stats<<<(NEXP * DD + 255) / 256, 256>>>();
        k_gemm<<<dim3((NN + 127) / 128, DD / 128, NEXP), 256>>>(
            conv_W + l * NEXP * DD * DD, conv_b + l * NEXP * DD);
        k_stats<<<(NEXP * DD + 255) / 256, 256>>>(bn_gamma + l * NEXP * DD,
                                                  bn_beta + l * NEXP * DD);
        k_combine<<<warpsBlocks, 256>>>(out, (l == NLAYER - 1) ? 1 : 0);
    }
}

// round 7
// speedup vs baseline: 1.0560x; 1.0560x over previous
#include <cuda_runtime.h>
#include <cuda_bf16.h>
#include <cstdint>

#define NN 50000
#define DD 256
#define NLAYER 3
#define NEXP 4
#define NED 1600000
#define NCAT 1024   // NEXP * DD

// ---------------- device scratch (static, no allocation) ----------------
__device__ float g_h[NN * DD];                      // 51.2 MB
__device__ __nv_bfloat16 g_A1[NN * DD];             // 25.6 MB (agg split hi)
__device__ __nv_bfloat16 g_A2[NN * DD];             // mid
__device__ __nv_bfloat16 g_A3[NN * DD];             // lo
__device__ __nv_bfloat16 g_B1[NLAYER * NCAT * DD];  // [l][fcat][k] W splits
__device__ __nv_bfloat16 g_B2[NLAYER * NCAT * DD];
__device__ __nv_bfloat16 g_B3[NLAYER * NCAT * DD];
__device__ float g_Y[NEXP * NN * DD];               // 204.8 MB (e*NN+n)*DD+f
__device__ float g_gates[NN * NEXP];
__device__ int   g_indptr[NN + 1];
__device__ int   g_cursor[NN];
__device__ int   g_col[NED];
__device__ int   g_indeg[NN];
__device__ int   g_outdeg[NN];
__device__ float g_norm_src[NN];
__device__ float g_norm_dst[NN];
__device__ float g_colsum[NCAT];
__device__ float g_colsq[NCAT];
__device__ float g_sA[NCAT];
__device__ float g_sB[NCAT];

// ---------------- helpers (sm_80-level PTX only) ----------------
__device__ __forceinline__ uint32_t smem_u32(const void* p) {
    uint32_t a;
    asm("{ .reg .u64 t; cvta.to.shared.u64 t, %1; cvt.u32.u64 %0, t; }" : "=r"(a) : "l"(p));
    return a;
}
__device__ __forceinline__ void ldsm_x4(uint32_t& r0, uint32_t& r1, uint32_t& r2,
                                        uint32_t& r3, uint32_t addr) {
    asm volatile("ldmatrix.sync.aligned.m8n8.x4.shared.b16 {%0,%1,%2,%3}, [%4];"
                 : "=r"(r0), "=r"(r1), "=r"(r2), "=r"(r3) : "r"(addr));
}
__device__ __forceinline__ void ldsm_x2(uint32_t& r0, uint32_t& r1, uint32_t addr) {
    asm volatile("ldmatrix.sync.aligned.m8n8.x2.shared.b16 {%0,%1}, [%2];"
                 : "=r"(r0), "=r"(r1) : "r"(addr));
}
__device__ __forceinline__ void mma_bf16(float* c, const uint32_t* a, const uint32_t* b) {
    asm volatile(
        "mma.sync.aligned.m16n8k16.row.col.f32.bf16.bf16.f32 "
        "{%0,%1,%2,%3}, {%4,%5,%6,%7}, {%8,%9}, {%0,%1,%2,%3};"
        : "+f"(c[0]), "+f"(c[1]), "+f"(c[2]), "+f"(c[3])
        : "r"(a[0]), "r"(a[1]), "r"(a[2]), "r"(a[3]), "r"(b[0]), "r"(b[1]));
}

// ---------------- graph preprocessing ----------------
__global__ void k_zero_deg() {
    int i = blockIdx.x * blockDim.x + threadIdx.x;
    if (i < NN) { g_indeg[i] = 0; g_outdeg[i] = 0; }
}
__global__ void k_degree(const int* __restrict__ ei) {
    int i = blockIdx.x * blockDim.x + threadIdx.x;
    if (i < NED) {
        atomicAdd(&g_outdeg[ei[i]], 1);
        atomicAdd(&g_indeg[ei[NED + i]], 1);
    }
}
__global__ void k_scan() {
    __shared__ int sbuf[1024];
    __shared__ int scarry;
    int tid = threadIdx.x;
    if (tid == 0) scarry = 0;
    __syncthreads();
    for (int base = 0; base < NN; base += 1024) {
        int i = base + tid;
        int v = (i < NN) ? g_indeg[i] : 0;
        sbuf[tid] = v;
        __syncthreads();
        for (int off = 1; off < 1024; off <<= 1) {
            int t = (tid >= off) ? sbuf[tid - off] : 0;
            __syncthreads();
            sbuf[tid] += t;
            __syncthreads();
        }
        if (i < NN) g_indptr[i] = scarry + sbuf[tid] - v;
        int tot = sbuf[1023];
        __syncthreads();
        if (tid == 0) scarry += tot;
        __syncthreads();
    }
    if (threadIdx.x == 0) g_indptr[NN] = scarry;
}
__global__ void k_norm() {
    int i = blockIdx.x * blockDim.x + threadIdx.x;
    if (i < NN) {
        g_norm_src[i] = rsqrtf(fmaxf((float)g_outdeg[i], 1.0f));
        g_norm_dst[i] = rsqrtf(fmaxf((float)g_indeg[i], 1.0f));
        g_cursor[i] = g_indptr[i];
    }
}
__global__ void k_fill(const int* __restrict__ ei) {
    int i = blockIdx.x * blockDim.x + threadIdx.x;
    if (i < NED) {
        int s = ei[i];
        int d = ei[NED + i];
        int p = atomicAdd(&g_cursor[d], 1);
        g_col[p] = s;
    }
}

// ---------------- embedding ----------------
__global__ void k_embed(const int* __restrict__ x, const float* __restrict__ emb) {
    int i = blockIdx.x * blockDim.x + threadIdx.x;
    if (i >= NN * 64) return;
    int n = i >> 6;
    int c = i & 63;
    ((float4*)g_h)[i] = ((const float4*)emb)[(long)x[n] * 64 + c];
}

// ---------------- W split to bf16 3-way (all layers, transposed [fcat][k]) ----------------
__global__ void k_wsplit(const float* __restrict__ W) {
    int t = blockIdx.x * blockDim.x + threadIdx.x;
    if (t >= NLAYER * NCAT * DD) return;
    int l = t / (NCAT * DD);
    int rem = t - l * (NCAT * DD);
    int fcat = rem >> 8;
    int k = rem & 255;
    int e = fcat >> 8;
    int f = fcat & 255;
    float v = W[(((long)l * NEXP + e) * DD + k) * DD + f];
    __nv_bfloat16 h1 = __float2bfloat16(v);
    float r1 = v - __bfloat162float(h1);
    __nv_bfloat16 h2 = __float2bfloat16(r1);
    float r2 = r1 - __bfloat162float(h2);
    __nv_bfloat16 h3 = __float2bfloat16(r2);
    g_B1[t] = h1;
    g_B2[t] = h2;
    g_B3[t] = h3;
}

// ---------------- gating: top-2 softmax ----------------
__global__ void k_gate(const float* __restrict__ wg) {
    int gw = (blockIdx.x * blockDim.x + threadIdx.x) >> 5;
    int lane = threadIdx.x & 31;
    if (gw >= NN) return;
    const float* hrow = g_h + gw * DD;
    const float4* w4 = (const float4*)wg;
    float ax = 0.f, ay = 0.f, az = 0.f, aw = 0.f;
#pragma unroll
    for (int j = 0; j < 8; j++) {
        int k = lane + 32 * j;
        float hv = hrow[k];
        float4 w = w4[k];
        ax += hv * w.x; ay += hv * w.y; az += hv * w.z; aw += hv * w.w;
    }
#pragma unroll
    for (int off = 16; off; off >>= 1) {
        ax += __shfl_xor_sync(0xFFFFFFFFu, ax, off);
        ay += __shfl_xor_sync(0xFFFFFFFFu, ay, off);
        az += __shfl_xor_sync(0xFFFFFFFFu, az, off);
        aw += __shfl_xor_sync(0xFFFFFFFFu, aw, off);
    }
    if (lane == 0) {
        float v[4] = {ax, ay, az, aw};
        int i1 = 0;
#pragma unroll
        for (int e = 1; e < 4; e++) if (v[e] > v[i1]) i1 = e;
        int i2 = (i1 == 0) ? 1 : 0;
#pragma unroll
        for (int e = 0; e < 4; e++) if (e != i1 && v[e] > v[i2]) i2 = e;
        float t = __expf(v[i2] - v[i1]);
        float inv = 1.0f / (1.0f + t);
        float go[4] = {0.f, 0.f, 0.f, 0.f};
        go[i1] = inv;
        go[i2] = t * inv;
        *(float4*)&g_gates[gw * 4] = make_float4(go[0], go[1], go[2], go[3]);
    }
}

// ---------------- SpMM: agg = Dd^-1/2 A Ds^-1/2 h  -> bf16 3-way split ----------------
__device__ __forceinline__ void split3_store(int idx, float4 v) {
    float vv[4] = {v.x, v.y, v.z, v.w};
    __nv_bfloat16 s1[4], s2[4], s3[4];
#pragma unroll
    for (int q = 0; q < 4; q++) {
        __nv_bfloat16 h1 = __float2bfloat16(vv[q]);
        float r1 = vv[q] - __bfloat162float(h1);
        __nv_bfloat16 h2 = __float2bfloat16(r1);
        float r2 = r1 - __bfloat162float(h2);
        s1[q] = h1; s2[q] = h2; s3[q] = __float2bfloat16(r2);
    }
    *(uint2*)(g_A1 + idx) = *(uint2*)s1;
    *(uint2*)(g_A2 + idx) = *(uint2*)s2;
    *(uint2*)(g_A3 + idx) = *(uint2*)s3;
}

__global__ void k_spmm() {
    int gw = (blockIdx.x * blockDim.x + threadIdx.x) >> 5;
    int lane = threadIdx.x & 31;
    if (gw >= NN) return;
    int beg = g_indptr[gw];
    int end = g_indptr[gw + 1];
    float4 a0 = make_float4(0.f, 0.f, 0.f, 0.f);
    float4 a1 = make_float4(0.f, 0.f, 0.f, 0.f);
    const float4* h4 = (const float4*)g_h;
    for (int p = beg; p < end; p++) {
        int s = __ldg(&g_col[p]);
        float ns = __ldg(&g_norm_src[s]);
        float4 v0 = h4[s * 64 + lane];
        float4 v1 = h4[s * 64 + 32 + lane];
        a0.x += ns * v0.x; a0.y += ns * v0.y; a0.z += ns * v0.z; a0.w += ns * v0.w;
        a1.x += ns * v1.x; a1.y += ns * v1.y; a1.z += ns * v1.z; a1.w += ns * v1.w;
    }
    float nd = g_norm_dst[gw];
    a0.x *= nd; a0.y *= nd; a0.z *= nd; a0.w *= nd;
    a1.x *= nd; a1.y *= nd; a1.z *= nd; a1.w *= nd;
    int base = gw * 256 + lane * 4;
    split3_store(base, a0);
    split3_store(base + 128, a1);
}

// ---------------- stats zero ----------------
__global__ void k_zero_stats() {
    int i = blockIdx.x * blockDim.x + threadIdx.x;
    if (i < NCAT) { g_colsum[i] = 0.f; g_colsq[i] = 0.f; }
}

// ---------------- mma.sync expert GEMM: 3-way split, 6 fused passes ----------------
// grid (391, 16), 256 threads. block tile M=128, N=64; K=256 in 8 chunks of 32.
// SMEM rows padded to 80B (stride 5 coprime 8 -> ldmatrix conflict-free, no swizzle).
// acc = a1b1 + a1b2 + a2b1 + a2b2 + a1b3 + a3b1   (error ~2^-26)
#define ROWB 80
#define OA1 0
#define OA2 10240
#define OA3 20480
#define OB1 30720
#define OB2 35840
#define OB3 40960
#define SM_TOT 46080

__global__ __launch_bounds__(256, 2) void k_gemm_mma(int l) {
    __shared__ __align__(128) char smem[SM_TOT];
    uint32_t sb = smem_u32(smem);
    int tid = threadIdx.x;
    int wid = tid >> 5;
    int lane = tid & 31;
    int wm = wid & 3;        // 4 m-stripes of 32 rows
    int wn = wid >> 2;       // 2 n-stripes of 32 cols
    int row0 = blockIdx.x * 128;
    int by = blockIdx.y;
    int e = by >> 2;
    int f0 = (by & 3) * 64;

    const __nv_bfloat16* B1G = g_B1 + (size_t)l * NCAT * DD;
    const __nv_bfloat16* B2G = g_B2 + (size_t)l * NCAT * DD;
    const __nv_bfloat16* B3G = g_B3 + (size_t)l * NCAT * DD;

    float acc[2][4][4];
#pragma unroll
    for (int mt = 0; mt < 2; mt++)
#pragma unroll
        for (int nt = 0; nt < 4; nt++)
#pragma unroll
            for (int q = 0; q < 4; q++) acc[mt][nt][q] = 0.f;

    // per-lane ldmatrix geometry
    int a_row = wm * 32 + (lane & 7) + ((lane >> 3) & 1) * 8;
    int a_kb = ((lane >> 4) & 1) * 16;
    int b_row = wn * 32 + (lane & 7);
    int b_kb = ((lane >> 3) & 1) * 16;

    // loader geometry: A 2 thr/row (2 x 16B segs each), B 4 thr/row (1 seg)
    int arr = tid >> 1, as0 = (tid & 1) * 2;
    int brr = tid >> 2, bsg = tid & 3;
    int agrow = row0 + arr;
    int bgrow = by * 64 + brr;

    for (int c = 0; c < 8; c++) {
        // ---- load chunk (k = c*32 .. +32) into padded SMEM ----
#pragma unroll
        for (int j = 0; j < 2; j++) {
            int seg = as0 + j;
            uint4 v1 = make_uint4(0, 0, 0, 0), v2 = v1, v3 = v1;
            if (agrow < NN) {
                int src = agrow * 256 + c * 32 + seg * 8;
                v1 = *(const uint4*)(g_A1 + src);
                v2 = *(const uint4*)(g_A2 + src);
                v3 = *(const uint4*)(g_A3 + src);
            }
            uint32_t d = (uint32_t)(arr * ROWB + seg * 16);
            *(uint4*)(smem + OA1 + d) = v1;
            *(uint4*)(smem + OA2 + d) = v2;
            *(uint4*)(smem + OA3 + d) = v3;
        }
        {
            int src = bgrow * 256 + c * 32 + bsg * 8;
            uint32_t d = (uint32_t)(brr * ROWB + bsg * 16);
            *(uint4*)(smem + OB1 + d) = *(const uint4*)(B1G + src);
            *(uint4*)(smem + OB2 + d) = *(const uint4*)(B2G + src);
            *(uint4*)(smem + OB3 + d) = *(const uint4*)(B3G + src);
        }
        __syncthreads();

        // ---- 2 k16-steps; load all 3 splits of frags, 6 mma-combos ----
#pragma unroll
        for (int ks = 0; ks < 2; ks++) {
            uint32_t a[3][2][4];
            uint32_t b[3][4][2];
            uint32_t akoff = (uint32_t)(ks * 32 + a_kb);
            uint32_t bkoff = (uint32_t)(ks * 32 + b_kb);
#pragma unroll
            for (int mt = 0; mt < 2; mt++) {
                uint32_t ro = (uint32_t)((a_row + mt * 16) * ROWB) + akoff;
                ldsm_x4(a[0][mt][0], a[0][mt][1], a[0][mt][2], a[0][mt][3], sb + OA1 + ro);
                ldsm_x4(a[1][mt][0], a[1][mt][1], a[1][mt][2], a[1][mt][3], sb + OA2 + ro);
                ldsm_x4(a[2][mt][0], a[2][mt][1], a[2][mt][2], a[2][mt][3], sb + OA3 + ro);
            }
#pragma unroll
            for (int nt = 0; nt < 4; nt++) {
                uint32_t ro = (uint32_t)((b_row + nt * 8) * ROWB) + bkoff;
                ldsm_x2(b[0][nt][0], b[0][nt][1], sb + OB1 + ro);
                ldsm_x2(b[1][nt][0], b[1][nt][1], sb + OB2 + ro);
                ldsm_x2(b[2][nt][0], b[2][nt][1], sb + OB3 + ro);
            }
#pragma unroll
            for (int mt = 0; mt < 2; mt++)
#pragma unroll
                for (int nt = 0; nt < 4; nt++) {
                    mma_bf16(acc[mt][nt], a[0][mt], b[0][nt]);  // a1*b1
                    mma_bf16(acc[mt][nt], a[0][mt], b[1][nt]);  // a1*b2
                    mma_bf16(acc[mt][nt], a[1][mt], b[0][nt]);  // a2*b1
                    mma_bf16(acc[mt][nt], a[1][mt], b[1][nt]);  // a2*b2
                    mma_bf16(acc[mt][nt], a[0][mt], b[2][nt]);  // a1*b3
                    mma_bf16(acc[mt][nt], a[2][mt], b[0][nt]);  // a3*b1
                }
        }
        __syncthreads();
    }

    // ---- epilogue: column stats + Y stores ----
    float ps[4][2], pq[4][2];
#pragma unroll
    for (int nt = 0; nt < 4; nt++) { ps[nt][0] = ps[nt][1] = pq[nt][0] = pq[nt][1] = 0.f; }
#pragma unroll
    for (int mt = 0; mt < 2; mt++)
#pragma unroll
        for (int nt = 0; nt < 4; nt++)
#pragma unroll
            for (int h = 0; h < 2; h++) {
                float v0 = acc[mt][nt][h * 2];
                float v1 = acc[mt][nt][h * 2 + 1];
                ps[nt][0] += v0; pq[nt][0] += v0 * v0;
                ps[nt][1] += v1; pq[nt][1] += v1 * v1;
            }
#pragma unroll
    for (int off = 4; off < 32; off <<= 1) {
#pragma unroll
        for (int nt = 0; nt < 4; nt++) {
            ps[nt][0] += __shfl_xor_sync(0xFFFFFFFFu, ps[nt][0], off);
            ps[nt][1] += __shfl_xor_sync(0xFFFFFFFFu, ps[nt][1], off);
            pq[nt][0] += __shfl_xor_sync(0xFFFFFFFFu, pq[nt][0], off);
            pq[nt][1] += __shfl_xor_sync(0xFFFFFFFFu, pq[nt][1], off);
        }
    }
    if (lane < 4) {
#pragma unroll
        for (int nt = 0; nt < 4; nt++) {
            int col = e * 256 + f0 + wn * 32 + nt * 8 + lane * 2;
            atomicAdd(&g_colsum[col], ps[nt][0]);
            atomicAdd(&g_colsum[col + 1], ps[nt][1]);
            atomicAdd(&g_colsq[col], pq[nt][0]);
            atomicAdd(&g_colsq[col + 1], pq[nt][1]);
        }
    }
#pragma unroll
    for (int mt = 0; mt < 2; mt++)
#pragma unroll
        for (int h = 0; h < 2; h++) {
            int grow = row0 + wm * 32 + mt * 16 + (lane >> 2) + h * 8;
            if (grow < NN) {
                float* base = g_Y + ((size_t)e * NN + grow) * 256 + f0 + wn * 32 + (lane & 3) * 2;
#pragma unroll
                for (int nt = 0; nt < 4; nt++)
                    *(float2*)(base + nt * 8) =
                        make_float2(acc[mt][nt][h * 2], acc[mt][nt][h * 2 + 1]);
            }
        }
}

// ---------------- BN fold ----------------
__global__ void k_stats(const float* __restrict__ gamma, const float* __restrict__ beta) {
    int i = blockIdx.x * blockDim.x + threadIdx.x;
    if (i < NCAT) {
        float mu = g_colsum[i] * (1.0f / NN);
        float ex2 = g_colsq[i] * (1.0f / NN);
        float var = fmaxf(ex2 - mu * mu, 0.f);
        float a = rsqrtf(var + 1e-5f) * gamma[i];
        g_sA[i] = a;
        g_sB[i] = beta[i] - mu * a;
    }
}

// ---------------- gated combine + residual-relu ----------------
__global__ void k_combine(float* __restrict__ dout, int last) {
    int gw = (blockIdx.x * blockDim.x + threadIdx.x) >> 5;
    int lane = threadIdx.x & 31;
    if (gw >= NN) return;
    float4 g4 = *(const float4*)&g_gates[gw * 4];
    float ga[4] = {g4.x, g4.y, g4.z, g4.w};
    const float4* Y4 = (const float4*)g_Y;
    const float4* A4 = (const float4*)g_sA;
    const float4* B4 = (const float4*)g_sB;
    float4 m0 = make_float4(0.f, 0.f, 0.f, 0.f);
    float4 m1 = make_float4(0.f, 0.f, 0.f, 0.f);
#pragma unroll
    for (int e = 0; e < 4; e++) {
        float ge = ga[e];
        if (ge == 0.f) continue;
        size_t base = ((size_t)e * NN + gw) * 64;
        float4 y0 = Y4[base + lane];
        float4 y1 = Y4[base + 32 + lane];
        float4 a0 = A4[e * 64 + lane];
        float4 a1 = A4[e * 64 + 32 + lane];
        float4 b0 = B4[e * 64 + lane];
        float4 b1 = B4[e * 64 + 32 + lane];
        m0.x += ge * (y0.x * a0.x + b0.x);
        m0.y += ge * (y0.y * a0.y + b0.y);
        m0.z += ge * (y0.z * a0.z + b0.z);
        m0.w += ge * (y0.w * a0.w + b0.w);
        m1.x += ge * (y1.x * a1.x + b1.x);
        m1.y += ge * (y1.y * a1.y + b1.y);
        m1.z += ge * (y1.z * a1.z + b1.z);
        m1.w += ge * (y1.w * a1.w + b1.w);
    }
    m0.x += fmaxf(m0.x, 0.f); m0.y += fmaxf(m0.y, 0.f);
    m0.z += fmaxf(m0.z, 0.f); m0.w += fmaxf(m0.w, 0.f);
    m1.x += fmaxf(m1.x, 0.f); m1.y += fmaxf(m1.y, 0.f);
    m1.z += fmaxf(m1.z, 0.f); m1.w += fmaxf(m1.w, 0.f);
    float4* hh = (float4*)g_h;
    hh[gw * 64 + lane] = m0;
    hh[gw * 64 + 32 + lane] = m1;
    if (last) {
        float4* oo = (float4*)dout;
        oo[gw * 64 + lane] = m0;
        oo[gw * 64 + 32 + lane] = m1;
    }
}

// ---------------- launch ----------------
extern "C" void kernel_launch(void* const* d_in, const int* in_sizes, int n_in,
                              void* d_out, int out_size) {
    const int*   x        = (const int*)d_in[0];
    const int*   ei       = (const int*)d_in[1];
    const float* emb      = (const float*)d_in[2];
    const float* w_gate   = (const float*)d_in[3];
    const float* conv_W   = (const float*)d_in[4];
    const float* bn_gamma = (const float*)d_in[6];
    const float* bn_beta  = (const float*)d_in[7];
    float* out = (float*)d_out;

    k_zero_deg<<<(NN + 255) / 256, 256>>>();
    k_degree<<<(NED + 255) / 256, 256>>>(ei);
    k_scan<<<1, 1024>>>();
    k_norm<<<(NN + 255) / 256, 256>>>();
    k_fill<<<(NED + 255) / 256, 256>>>(ei);
    k_embed<<<(NN * 64 + 255) / 256, 256>>>(x, emb);
    k_wsplit<<<(NLAYER * NCAT * DD + 255) / 256, 256>>>(conv_W);

    const int warpsBlocks = (NN * 32 + 255) / 256;
    for (int l = 0; l < NLAYER; l++) {
        k_gate<<<warpsBlocks, 256>>>(w_gate + l * DD * NEXP);
        k_spmm<<<warpsBlocks, 256>>>();
        k_zero_stats<<<(NCAT + 255) / 256, 256>>>();
        k_gemm_mma<<<dim3((NN + 127) / 128, 16), 256>>>(l);
        k_stats<<<(NCAT + 255) / 256, 256>>>(bn_gamma + l * NCAT, bn_beta + l * NCAT);
        k_combine<<<warpsBlocks, 256>>>(out, (l == NLAYER - 1) ? 1 : 0);
    }
}

// round 14
// speedup vs baseline: 1.5956x; 1.5110x over previous
#include <cuda_runtime.h>
#include <cuda_fp16.h>
#include <cstdint>

#define NN 50000
#define DD 256
#define NLAYER 3
#define NEXP 4
#define NED 1600000
#define NCAT 1024   // NEXP * DD
#define RSCALE 2048.0f
#define RINV (1.0f / 2048.0f)

// ---------------- device scratch (static, no allocation) ----------------
__device__ float g_h[NN * DD];                 // 51.2 MB
__device__ __half g_A1[NN * DD];               // 25.6 MB (agg fp16 hi)
__device__ __half g_A2[NN * DD];               // residual * 2048 (normal-range)
__device__ __half g_B1[NLAYER * NCAT * DD];    // [l][fcat][k] W hi
__device__ __half g_B2[NLAYER * NCAT * DD];    // residual * 2048
__device__ float g_Y[NEXP * NN * DD];          // 204.8 MB (e*NN+n)*DD+f
__device__ float g_gates[NN * NEXP];
__device__ int   g_indptr[NN + 1];
__device__ int   g_cursor[NN];
__device__ int   g_col[NED];
__device__ int   g_indeg[NN];
__device__ int   g_outdeg[NN];
__device__ float g_norm_src[NN];
__device__ float g_norm_dst[NN];
__device__ float g_colsum[NCAT];
__device__ float g_colsq[NCAT];
__device__ float g_sA[NCAT];
__device__ float g_sB[NCAT];

// ---------------- helpers (sm_80-level PTX only) ----------------
__device__ __forceinline__ uint32_t smem_u32(const void* p) {
    uint32_t a;
    asm("{ .reg .u64 t; cvta.to.shared.u64 t, %1; cvt.u32.u64 %0, t; }" : "=r"(a) : "l"(p));
    return a;
}
__device__ __forceinline__ void ldsm_x4(uint32_t& r0, uint32_t& r1, uint32_t& r2,
                                        uint32_t& r3, uint32_t addr) {
    asm volatile("ldmatrix.sync.aligned.m8n8.x4.shared.b16 {%0,%1,%2,%3}, [%4];"
                 : "=r"(r0), "=r"(r1), "=r"(r2), "=r"(r3) : "r"(addr));
}
__device__ __forceinline__ void mma_f16(float* c, const uint32_t* a, const uint32_t* b) {
    asm volatile(
        "mma.sync.aligned.m16n8k16.row.col.f32.f16.f16.f32 "
        "{%0,%1,%2,%3}, {%4,%5,%6,%7}, {%8,%9}, {%0,%1,%2,%3};"
        : "+f"(c[0]), "+f"(c[1]), "+f"(c[2]), "+f"(c[3])
        : "r"(a[0]), "r"(a[1]), "r"(a[2]), "r"(a[3]), "r"(b[0]), "r"(b[1]));
}
__device__ __forceinline__ void cpa16(uint32_t dst, const void* src) {
    asm volatile("cp.async.ca.shared.global [%0], [%1], 16;" :: "r"(dst), "l"(src));
}
__device__ __forceinline__ void cpa16p(uint32_t dst, const void* src, int full) {
    asm volatile("cp.async.ca.shared.global [%0], [%1], 16, %2;"
                 :: "r"(dst), "l"(src), "r"(full) : "memory");
}
__device__ __forceinline__ void cpa_wait_all() {
    asm volatile("cp.async.commit_group;" ::: "memory");
    asm volatile("cp.async.wait_group 0;" ::: "memory");
}

// ---------------- graph preprocessing ----------------
__global__ void k_zero_deg() {
    int i = blockIdx.x * blockDim.x + threadIdx.x;
    if (i < NN) { g_indeg[i] = 0; g_outdeg[i] = 0; }
}
__global__ void k_degree(const int* __restrict__ ei) {
    int i = blockIdx.x * blockDim.x + threadIdx.x;
    if (i < NED) {
        atomicAdd(&g_outdeg[ei[i]], 1);
        atomicAdd(&g_indeg[ei[NED + i]], 1);
    }
}
__global__ void k_scan() {
    __shared__ int sbuf[1024];
    __shared__ int scarry;
    int tid = threadIdx.x;
    if (tid == 0) scarry = 0;
    __syncthreads();
    for (int base = 0; base < NN; base += 1024) {
        int i = base + tid;
        int v = (i < NN) ? g_indeg[i] : 0;
        sbuf[tid] = v;
        __syncthreads();
        for (int off = 1; off < 1024; off <<= 1) {
            int t = (tid >= off) ? sbuf[tid - off] : 0;
            __syncthreads();
            sbuf[tid] += t;
            __syncthreads();
        }
        if (i < NN) g_indptr[i] = scarry + sbuf[tid] - v;
        int tot = sbuf[1023];
        __syncthreads();
        if (tid == 0) scarry += tot;
        __syncthreads();
    }
    if (threadIdx.x == 0) g_indptr[NN] = scarry;
}
__global__ void k_norm() {
    int i = blockIdx.x * blockDim.x + threadIdx.x;
    if (i < NN) {
        g_norm_src[i] = rsqrtf(fmaxf((float)g_outdeg[i], 1.0f));
        g_norm_dst[i] = rsqrtf(fmaxf((float)g_indeg[i], 1.0f));
        g_cursor[i] = g_indptr[i];
    }
}
__global__ void k_fill(const int* __restrict__ ei) {
    int i = blockIdx.x * blockDim.x + threadIdx.x;
    if (i < NED) {
        int s = ei[i];
        int d = ei[NED + i];
        int p = atomicAdd(&g_cursor[d], 1);
        g_col[p] = s;
    }
}

// ---------------- embedding ----------------
__global__ void k_embed(const int* __restrict__ x, const float* __restrict__ emb) {
    int i = blockIdx.x * blockDim.x + threadIdx.x;
    if (i >= NN * 64) return;
    int n = i >> 6;
    int c = i & 63;
    ((float4*)g_h)[i] = ((const float4*)emb)[(long)x[n] * 64 + c];
}

// ------- W split: fp16 hi + scaled residual (all layers, transposed [fcat][k]) ---
__global__ void k_wsplit(const float* __restrict__ W) {
    int t = blockIdx.x * blockDim.x + threadIdx.x;
    if (t >= NLAYER * NCAT * DD) return;
    int l = t / (NCAT * DD);
    int rem = t - l * (NCAT * DD);
    int fcat = rem >> 8;
    int k = rem & 255;
    int e = fcat >> 8;
    int f = fcat & 255;
    float v = W[(((long)l * NEXP + e) * DD + k) * DD + f];
    __half h1 = __float2half_rn(v);
    float r1 = (v - __half2float(h1)) * RSCALE;   // lift residual to normal range
    g_B1[t] = h1;
    g_B2[t] = __float2half_rn(r1);
}

// ---------------- gating: top-2 softmax ----------------
__global__ void k_gate(const float* __restrict__ wg) {
    int gw = (blockIdx.x * blockDim.x + threadIdx.x) >> 5;
    int lane = threadIdx.x & 31;
    if (gw >= NN) return;
    const float* hrow = g_h + gw * DD;
    const float4* w4 = (const float4*)wg;
    float ax = 0.f, ay = 0.f, az = 0.f, aw = 0.f;
#pragma unroll
    for (int j = 0; j < 8; j++) {
        int k = lane + 32 * j;
        float hv = hrow[k];
        float4 w = w4[k];
        ax += hv * w.x; ay += hv * w.y; az += hv * w.z; aw += hv * w.w;
    }
#pragma unroll
    for (int off = 16; off; off >>= 1) {
        ax += __shfl_xor_sync(0xFFFFFFFFu, ax, off);
        ay += __shfl_xor_sync(0xFFFFFFFFu, ay, off);
        az += __shfl_xor_sync(0xFFFFFFFFu, az, off);
        aw += __shfl_xor_sync(0xFFFFFFFFu, aw, off);
    }
    if (lane == 0) {
        float v[4] = {ax, ay, az, aw};
        int i1 = 0;
#pragma unroll
        for (int e = 1; e < 4; e++) if (v[e] > v[i1]) i1 = e;
        int i2 = (i1 == 0) ? 1 : 0;
#pragma unroll
        for (int e = 0; e < 4; e++) if (e != i1 && v[e] > v[i2]) i2 = e;
        float t = __expf(v[i2] - v[i1]);
        float inv = 1.0f / (1.0f + t);
        float go[4] = {0.f, 0.f, 0.f, 0.f};
        go[i1] = inv;
        go[i2] = t * inv;
        *(float4*)&g_gates[gw * 4] = make_float4(go[0], go[1], go[2], go[3]);
    }
}

// ------ SpMM: agg = Dd^-1/2 A Ds^-1/2 h -> fp16 hi + scaled residual ------------
__device__ __forceinline__ void split2_store(int idx, float4 v) {
    float vv[4] = {v.x, v.y, v.z, v.w};
    __half s1[4], s2[4];
#pragma unroll
    for (int q = 0; q < 4; q++) {
        __half h1 = __float2half_rn(vv[q]);
        float r1 = (vv[q] - __half2float(h1)) * RSCALE;
        s1[q] = h1;
        s2[q] = __float2half_rn(r1);
    }
    *(uint2*)(g_A1 + idx) = *(uint2*)s1;
    *(uint2*)(g_A2 + idx) = *(uint2*)s2;
}

__global__ void k_spmm() {
    int gw = (blockIdx.x * blockDim.x + threadIdx.x) >> 5;
    int lane = threadIdx.x & 31;
    if (gw >= NN) return;
    int beg = g_indptr[gw];
    int end = g_indptr[gw + 1];
    float4 a0 = make_float4(0.f, 0.f, 0.f, 0.f);
    float4 a1 = make_float4(0.f, 0.f, 0.f, 0.f);
    const float4* h4 = (const float4*)g_h;
    for (int p = beg; p < end; p++) {
        int s = __ldg(&g_col[p]);
        float ns = __ldg(&g_norm_src[s]);
        float4 v0 = h4[s * 64 + lane];
        float4 v1 = h4[s * 64 + 32 + lane];
        a0.x += ns * v0.x; a0.y += ns * v0.y; a0.z += ns * v0.z; a0.w += ns * v0.w;
        a1.x += ns * v1.x; a1.y += ns * v1.y; a1.z += ns * v1.z; a1.w += ns * v1.w;
    }
    float nd = g_norm_dst[gw];
    a0.x *= nd; a0.y *= nd; a0.z *= nd; a0.w *= nd;
    a1.x *= nd; a1.y *= nd; a1.z *= nd; a1.w *= nd;
    int base = gw * 256 + lane * 4;
    split2_store(base, a0);
    split2_store(base + 128, a1);
}

// ---------------- stats zero ----------------
__global__ void k_zero_stats() {
    int i = blockIdx.x * blockDim.x + threadIdx.x;
    if (i < NCAT) { g_colsum[i] = 0.f; g_colsq[i] = 0.f; }
}

// ------ mma.sync expert GEMM: scaled-residual fp16, 3 passes, 2 accumulators ----
// grid (391, 16), 256 threads. block tile M=128, N=64; K=256 in 8 chunks of 32.
// SMEM rows padded to 80B (stride 5 coprime 8 -> ldmatrix conflict-free).
// acc0 = a1*b1 ; acc1 = a1*b2' + a2'*b1 ; result = acc0 + acc1/2048
// error ~2^-24 (dropped a2b2 + rep residuals), no fp16 denormal operands.
#define ROWB 80
#define OA1 0
#define OA2 10240
#define OB1 20480
#define OB2 25600
#define SM_TOT 30720

__global__ __launch_bounds__(256, 2) void k_gemm_mma(int l) {
    __shared__ __align__(128) char smem[SM_TOT];
    uint32_t sb = smem_u32(smem);
    int tid = threadIdx.x;
    int wid = tid >> 5;
    int lane = tid & 31;
    int wm = wid & 3;        // 4 m-stripes of 32 rows
    int wn = wid >> 2;       // 2 n-stripes of 32 cols
    int row0 = blockIdx.x * 128;
    int by = blockIdx.y;
    int e = by >> 2;
    int f0 = (by & 3) * 64;

    const __half* B1G = g_B1 + (size_t)l * NCAT * DD;
    const __half* B2G = g_B2 + (size_t)l * NCAT * DD;

    float acc0[2][4][4], acc1[2][4][4];
#pragma unroll
    for (int mt = 0; mt < 2; mt++)
#pragma unroll
        for (int nt = 0; nt < 4; nt++)
#pragma unroll
            for (int q = 0; q < 4; q++) { acc0[mt][nt][q] = 0.f; acc1[mt][nt][q] = 0.f; }

    // per-lane ldmatrix geometry
    int a_row = wm * 32 + (lane & 7) + ((lane >> 3) & 1) * 8;
    int a_kb = ((lane >> 4) & 1) * 16;
    // B x4 geometry: pair p covers n-tiles {2p, 2p+1}; 16 rows
    int b_row = wn * 32 + (lane & 7) + ((lane >> 4) & 1) * 8;
    int b_kb = ((lane >> 3) & 1) * 16;

    // loader geometry: A 2 thr/row (2 x 16B segs each), B 4 thr/row (1 seg)
    int arr = tid >> 1, as0 = (tid & 1) * 2;
    int brr = tid >> 2, bsg = tid & 3;
    int agrow = row0 + arr;
    int bgrow = by * 64 + brr;
    int afull = (agrow < NN) ? 16 : 0;
    const __half* a1src0 = g_A1 + ((agrow < NN) ? (agrow * 256) : 0);
    const __half* a2src0 = g_A2 + ((agrow < NN) ? (agrow * 256) : 0);

    for (int c = 0; c < 8; c++) {
        // ---- async-load chunk (k = c*32 .. +32) into padded SMEM ----
#pragma unroll
        for (int j = 0; j < 2; j++) {
            int seg = as0 + j;
            uint32_t d = sb + (uint32_t)(arr * ROWB + seg * 16);
            int so = c * 32 + seg * 8;
            cpa16p(d + OA1, a1src0 + so, afull);
            cpa16p(d + OA2, a2src0 + so, afull);
        }
        {
            uint32_t d = sb + (uint32_t)(brr * ROWB + bsg * 16);
            int so = bgrow * 256 + c * 32 + bsg * 8;
            cpa16(d + OB1, B1G + so);
            cpa16(d + OB2, B2G + so);
        }
        cpa_wait_all();
        __syncthreads();

        // ---- 2 k16-steps; 3 mma-combos per tile (2 accumulators) ----
#pragma unroll
        for (int ks = 0; ks < 2; ks++) {
            uint32_t a[2][2][4];
            uint32_t b[2][4][2];
            uint32_t akoff = (uint32_t)(ks * 32 + a_kb);
            uint32_t bkoff = (uint32_t)(ks * 32 + b_kb);
#pragma unroll
            for (int mt = 0; mt < 2; mt++) {
                uint32_t ro = (uint32_t)((a_row + mt * 16) * ROWB) + akoff;
                ldsm_x4(a[0][mt][0], a[0][mt][1], a[0][mt][2], a[0][mt][3], sb + OA1 + ro);
                ldsm_x4(a[1][mt][0], a[1][mt][1], a[1][mt][2], a[1][mt][3], sb + OA2 + ro);
            }
#pragma unroll
            for (int p = 0; p < 2; p++) {
                uint32_t ro = (uint32_t)((b_row + p * 16) * ROWB) + bkoff;
                ldsm_x4(b[0][2 * p][0], b[0][2 * p][1], b[0][2 * p + 1][0],
                        b[0][2 * p + 1][1], sb + OB1 + ro);
                ldsm_x4(b[1][2 * p][0], b[1][2 * p][1], b[1][2 * p + 1][0],
                        b[1][2 * p + 1][1], sb + OB2 + ro);
            }
#pragma unroll
            for (int mt = 0; mt < 2; mt++)
#pragma unroll
                for (int nt = 0; nt < 4; nt++) {
                    mma_f16(acc0[mt][nt], a[0][mt], b[0][nt]);  // a1*b1
                    mma_f16(acc1[mt][nt], a[0][mt], b[1][nt]);  // a1*b2'
                    mma_f16(acc1[mt][nt], a[1][mt], b[0][nt]);  // a2'*b1
                }
        }
        __syncthreads();
    }

    // fold scaled cross terms: v = acc0 + acc1/2048
#pragma unroll
    for (int mt = 0; mt < 2; mt++)
#pragma unroll
        for (int nt = 0; nt < 4; nt++)
#pragma unroll
            for (int q = 0; q < 4; q++)
                acc0[mt][nt][q] = fmaf(acc1[mt][nt][q], RINV, acc0[mt][nt][q]);

    // ---- epilogue: column stats + Y stores ----
    float ps[4][2], pq[4][2];
#pragma unroll
    for (int nt = 0; nt < 4; nt++) { ps[nt][0] = ps[nt][1] = pq[nt][0] = pq[nt][1] = 0.f; }
#pragma unroll
    for (int mt = 0; mt < 2; mt++)
#pragma unroll
        for (int nt = 0; nt < 4; nt++)
#pragma unroll
            for (int h = 0; h < 2; h++) {
                float v0 = acc0[mt][nt][h * 2];
                float v1 = acc0[mt][nt][h * 2 + 1];
                ps[nt][0] += v0; pq[nt][0] += v0 * v0;
                ps[nt][1] += v1; pq[nt][1] += v1 * v1;
            }
#pragma unroll
    for (int off = 4; off < 32; off <<= 1) {
#pragma unroll
        for (int nt = 0; nt < 4; nt++) {
            ps[nt][0] += __shfl_xor_sync(0xFFFFFFFFu, ps[nt][0], off);
            ps[nt][1] += __shfl_xor_sync(0xFFFFFFFFu, ps[nt][1], off);
            pq[nt][0] += __shfl_xor_sync(0xFFFFFFFFu, pq[nt][0], off);
            pq[nt][1] += __shfl_xor_sync(0xFFFFFFFFu, pq[nt][1], off);
        }
    }
    if (lane < 4) {
#pragma unroll
        for (int nt = 0; nt < 4; nt++) {
            int col = e * 256 + f0 + wn * 32 + nt * 8 + lane * 2;
            atomicAdd(&g_colsum[col], ps[nt][0]);
            atomicAdd(&g_colsum[col + 1], ps[nt][1]);
            atomicAdd(&g_colsq[col], pq[nt][0]);
            atomicAdd(&g_colsq[col + 1], pq[nt][1]);
        }
    }
#pragma unroll
    for (int mt = 0; mt < 2; mt++)
#pragma unroll
        for (int h = 0; h < 2; h++) {
            int grow = row0 + wm * 32 + mt * 16 + (lane >> 2) + h * 8;
            if (grow < NN) {
                float* base = g_Y + ((size_t)e * NN + grow) * 256 + f0 + wn * 32 + (lane & 3) * 2;
#pragma unroll
                for (int nt = 0; nt < 4; nt++)
                    *(float2*)(base + nt * 8) =
                        make_float2(acc0[mt][nt][h * 2], acc0[mt][nt][h * 2 + 1]);
            }
        }
}

// ---------------- BN fold ----------------
__global__ void k_stats(const float* __restrict__ gamma, const float* __restrict__ beta) {
    int i = blockIdx.x * blockDim.x + threadIdx.x;
    if (i < NCAT) {
        float mu = g_colsum[i] * (1.0f / NN);
        float ex2 = g_colsq[i] * (1.0f / NN);
        float var = fmaxf(ex2 - mu * mu, 0.f);
        float a = rsqrtf(var + 1e-5f) * gamma[i];
        g_sA[i] = a;
        g_sB[i] = beta[i] - mu * a;
    }
}

// ---------------- gated combine + residual-relu ----------------
__global__ void k_combine(float* __restrict__ dout, int last) {
    int gw = (blockIdx.x * blockDim.x + threadIdx.x) >> 5;
    int lane = threadIdx.x & 31;
    if (gw >= NN) return;
    float4 g4 = *(const float4*)&g_gates[gw * 4];
    float ga[4] = {g4.x, g4.y, g4.z, g4.w};
    const float4* Y4 = (const float4*)g_Y;
    const float4* A4 = (const float4*)g_sA;
    const float4* B4 = (const float4*)g_sB;
    float4 m0 = make_float4(0.f, 0.f, 0.f, 0.f);
    float4 m1 = make_float4(0.f, 0.f, 0.f, 0.f);
#pragma unroll
    for (int e = 0; e < 4; e++) {
        float ge = ga[e];
        if (ge == 0.f) continue;
        size_t base = ((size_t)e * NN + gw) * 64;
        float4 y0 = Y4[base + lane];
        float4 y1 = Y4[base + 32 + lane];
        float4 a0 = A4[e * 64 + lane];
        float4 a1 = A4[e * 64 + 32 + lane];
        float4 b0 = B4[e * 64 + lane];
        float4 b1 = B4[e * 64 + 32 + lane];
        m0.x += ge * (y0.x * a0.x + b0.x);
        m0.y += ge * (y0.y * a0.y + b0.y);
        m0.z += ge * (y0.z * a0.z + b0.z);
        m0.w += ge * (y0.w * a0.w + b0.w);
        m1.x += ge * (y1.x * a1.x + b1.x);
        m1.y += ge * (y1.y * a1.y + b1.y);
        m1.z += ge * (y1.z * a1.z + b1.z);
        m1.w += ge * (y1.w * a1.w + b1.w);
    }
    m0.x += fmaxf(m0.x, 0.f); m0.y += fmaxf(m0.y, 0.f);
    m0.z += fmaxf(m0.z, 0.f); m0.w += fmaxf(m0.w, 0.f);
    m1.x += fmaxf(m1.x, 0.f); m1.y += fmaxf(m1.y, 0.f);
    m1.z += fmaxf(m1.z, 0.f); m1.w += fmaxf(m1.w, 0.f);
    float4* hh = (float4*)g_h;
    hh[gw * 64 + lane] = m0;
    hh[gw * 64 + 32 + lane] = m1;
    if (last) {
        float4* oo = (float4*)dout;
        oo[gw * 64 + lane] = m0;
        oo[gw * 64 + 32 + lane] = m1;
    }
}

// ---------------- launch ----------------
extern "C" void kernel_launch(void* const* d_in, const int* in_sizes, int n_in,
                              void* d_out, int out_size) {
    const int*   x        = (const int*)d_in[0];
    const int*   ei       = (const int*)d_in[1];
    const float* emb      = (const float*)d_in[2];
    const float* w_gate   = (const float*)d_in[3];
    const float* conv_W   = (const float*)d_in[4];
    const float* bn_gamma = (const float*)d_in[6];
    const float* bn_beta  = (const float*)d_in[7];
    float* out = (float*)d_out;

    k_zero_deg<<<(NN + 255) / 256, 256>>>();
    k_degree<<<(NED + 255) / 256, 256>>>(ei);
    k_scan<<<1, 1024>>>();
    k_norm<<<(NN + 255) / 256, 256>>>();
    k_fill<<<(NED + 255) / 256, 256>>>(ei);
    k_embed<<<(NN * 64 + 255) / 256, 256>>>(x, emb);
    k_wsplit<<<(NLAYER * NCAT * DD + 255) / 256, 256>>>(conv_W);

    const int warpsBlocks = (NN * 32 + 255) / 256;
    for (int l = 0; l < NLAYER; l++) {
        k_gate<<<warpsBlocks, 256>>>(w_gate + l * DD * NEXP);
        k_spmm<<<warpsBlocks, 256>>>();
        k_zero_stats<<<(NCAT + 255) / 256, 256>>>();
        k_gemm_mma<<<dim3((NN + 127) / 128, 16), 256>>>(l);
        k_stats<<<(NCAT + 255) / 256, 256>>>(bn_gamma + l * NCAT, bn_beta + l * NCAT);
        k_combine<<<warpsBlocks, 256>>>(out, (l == NLAYER - 1) ? 1 : 0);
    }
}